// round 7
// baseline (speedup 1.0000x reference)
#include <cuda_runtime.h>
#include <float.h>

// Problem constants (fixed shapes)
#define NG    128
#define NPG   64
#define EPG   1024
#define ETOT  131072
#define HD    128
#define FD    384      // 3*H
#define KSEL  32
#define DOUT  10
#define NT    512      // 16 warps

// padded strides (floats) — all ≡ 4 (mod 32) banks so 4 row-groups hit distinct banks
#define SA    68       // adjacency row stride
#define SX    132      // x tile row stride
#define SF    388      // feats row stride

// Shared memory layout (float indices)
#define OFF_A     0                       // 64*68   = 4352
#define OFF_XS    4352                    // 64*132  = 8448
#define OFF_TMPI  12800                   // 32*256  = 8192 (k-pair interleaved AXW buffer)
#define OFF_FEATS 20992                   // 64*388  = 24832
#define OFF_WC    45824                   // 32*256  = 8192 (interleaved W stage; reused as psum)
#define OFF_SCORE 54016                   // 64
#define OFF_TVEC  54080                   // 64
#define OFF_SLIST 54144                   // 32 (int)
#define OFF_SCNT  54176                   // 4
#define OFF_RD    54180                   // 768
#define OFF_T1    54948                   // 128
#define OFF_T2    55076                   // 64
#define OFF_WAS   55140                   // 384
#define SMEM_FLOATS 55524                 // 222096 bytes

// packed f32x2 FMA: acc.lo += a.lo*b.lo ; acc.hi += a.hi*b.hi
__device__ __forceinline__ void fma2(unsigned long long& acc,
                                     unsigned long long a, unsigned long long b)
{
    asm("fma.rn.f32x2 %0, %1, %2, %0;" : "+l"(acc) : "l"(a), "l"(b));
}

__device__ __forceinline__ float red2(unsigned long long v)
{
    float2 f = *(float2*)&v;
    return f.x + f.y;
}

// ---------------------------------------------------------------------------
// tmpI (k-pair interleaved [j2][c*2+par]) = In[64][128] @ Wg[128][128]
// In: smem, row stride inStride, k-contiguous. W staged interleaved in Wc.
// warp tile 16 rows x 32 cols; thread tile 4x4. lane: lr=l&3 (row), lc=l>>2 (col)
// ---------------------------------------------------------------------------
__device__ __forceinline__ void gemm_xw(const float* __restrict__ In, int inStride,
                                        const float* __restrict__ Wg,
                                        float* __restrict__ Wc, float* __restrict__ tmpI,
                                        int tid, int wr, int wc, int lr, int lc)
{
    unsigned long long acc[4][4];
#pragma unroll
    for (int r = 0; r < 4; ++r)
#pragma unroll
        for (int c = 0; c < 4; ++c) acc[r][c] = 0ull;

    const int colBase = wc * 32 + lc * 4;

    for (int kc = 0; kc < 128; kc += 64) {
        __syncthreads();  // protect Wc reuse; orders feats writes before reads
        // stage 64 k-rows of W, interleaved by k-parity: Wc[k2*256 + c*2 + par]
#pragma unroll
        for (int it = 0; it < 2; ++it) {
            int lin = it * 512 + tid;      // 0..1023
            int k2  = lin >> 5;            // 0..31
            int cq  = lin & 31;            // 0..31
            float4 e = *(const float4*)(Wg + (kc + 2 * k2) * HD + cq * 4);
            float4 o = *(const float4*)(Wg + (kc + 2 * k2 + 1) * HD + cq * 4);
            float4* dst = (float4*)(Wc + k2 * 256 + cq * 8);
            dst[0] = make_float4(e.x, o.x, e.y, o.y);
            dst[1] = make_float4(e.z, o.z, e.w, o.w);
        }
        __syncthreads();
#pragma unroll 4
        for (int k2 = 0; k2 < 32; k2 += 2) {  // one k-quad per iter
            ulonglong2 a[4];
#pragma unroll
            for (int ri = 0; ri < 4; ++ri) {
                int row = wr * 16 + ri * 4 + lr;
                a[ri] = *(const ulonglong2*)(In + row * inStride + kc + k2 * 2);
            }
            ulonglong2 wA = *(const ulonglong2*)(Wc + k2 * 256 + colBase * 2);
            ulonglong2 wB = *(const ulonglong2*)(Wc + k2 * 256 + colBase * 2 + 4);
            ulonglong2 wC = *(const ulonglong2*)(Wc + (k2 + 1) * 256 + colBase * 2);
            ulonglong2 wD = *(const ulonglong2*)(Wc + (k2 + 1) * 256 + colBase * 2 + 4);
#pragma unroll
            for (int ri = 0; ri < 4; ++ri) {
                fma2(acc[ri][0], a[ri].x, wA.x);
                fma2(acc[ri][1], a[ri].x, wA.y);
                fma2(acc[ri][2], a[ri].x, wB.x);
                fma2(acc[ri][3], a[ri].x, wB.y);
                fma2(acc[ri][0], a[ri].y, wC.x);
                fma2(acc[ri][1], a[ri].y, wC.y);
                fma2(acc[ri][2], a[ri].y, wD.x);
                fma2(acc[ri][3], a[ri].y, wD.y);
            }
        }
    }
    // write result interleaved by row parity: tmpI[(row>>1)*256 + c*2 + (row&1)]
#pragma unroll
    for (int ri = 0; ri < 4; ++ri) {
        int row = wr * 16 + ri * 4 + lr;
        float* dst = tmpI + (row >> 1) * 256 + (row & 1);
#pragma unroll
        for (int cj = 0; cj < 4; ++cj)
            dst[(colBase + cj) * 2] = red2(acc[ri][cj]);
    }
}

// ---------------------------------------------------------------------------
// featsDst[64][SF] = relu(A[64][64](stride SA) @ tmpI + b)
// ---------------------------------------------------------------------------
__device__ __forceinline__ void amult_relu(const float* __restrict__ A,
                                           const float* __restrict__ tmpI,
                                           const float* __restrict__ bvec,
                                           float* __restrict__ featsDst,
                                           int wr, int wc, int lr, int lc)
{
    unsigned long long acc[4][4];
#pragma unroll
    for (int r = 0; r < 4; ++r)
#pragma unroll
        for (int c = 0; c < 4; ++c) acc[r][c] = 0ull;

    const int colBase = wc * 32 + lc * 4;
    __syncthreads();  // tmpI writes visible
#pragma unroll 4
    for (int j2 = 0; j2 < 32; j2 += 2) {  // j-quad
        ulonglong2 a[4];
#pragma unroll
        for (int ri = 0; ri < 4; ++ri) {
            int row = wr * 16 + ri * 4 + lr;
            a[ri] = *(const ulonglong2*)(A + row * SA + j2 * 2);
        }
        ulonglong2 tA = *(const ulonglong2*)(tmpI + j2 * 256 + colBase * 2);
        ulonglong2 tB = *(const ulonglong2*)(tmpI + j2 * 256 + colBase * 2 + 4);
        ulonglong2 tC = *(const ulonglong2*)(tmpI + (j2 + 1) * 256 + colBase * 2);
        ulonglong2 tD = *(const ulonglong2*)(tmpI + (j2 + 1) * 256 + colBase * 2 + 4);
#pragma unroll
        for (int ri = 0; ri < 4; ++ri) {
            fma2(acc[ri][0], a[ri].x, tA.x);
            fma2(acc[ri][1], a[ri].x, tA.y);
            fma2(acc[ri][2], a[ri].x, tB.x);
            fma2(acc[ri][3], a[ri].x, tB.y);
            fma2(acc[ri][0], a[ri].y, tC.x);
            fma2(acc[ri][1], a[ri].y, tC.y);
            fma2(acc[ri][2], a[ri].y, tD.x);
            fma2(acc[ri][3], a[ri].y, tD.y);
        }
    }
    float4 bb = *(const float4*)(bvec + colBase);
#pragma unroll
    for (int ri = 0; ri < 4; ++ri) {
        int row = wr * 16 + ri * 4 + lr;
        float4 v;
        v.x = fmaxf(red2(acc[ri][0]) + bb.x, 0.f);
        v.y = fmaxf(red2(acc[ri][1]) + bb.y, 0.f);
        v.z = fmaxf(red2(acc[ri][2]) + bb.z, 0.f);
        v.w = fmaxf(red2(acc[ri][3]) + bb.w, 0.f);
        *(float4*)(featsDst + row * SF + colBase) = v;
    }
    __syncthreads();
}

__global__ void __launch_bounds__(NT, 1)
sagpool_kernel(const float* __restrict__ x, const int* __restrict__ ei,
               const float* __restrict__ W1, const float* __restrict__ b1,
               const float* __restrict__ W2, const float* __restrict__ b2,
               const float* __restrict__ W3, const float* __restrict__ b3,
               const float* __restrict__ Wa, const float* __restrict__ ba,
               const float* __restrict__ M1, const float* __restrict__ c1,
               const float* __restrict__ M2, const float* __restrict__ c2,
               const float* __restrict__ M3, const float* __restrict__ c3,
               float* __restrict__ out)
{
    extern __shared__ float sm[];
    float* A     = sm + OFF_A;
    float* xs    = sm + OFF_XS;
    float* tmpI  = sm + OFF_TMPI;
    float* feats = sm + OFF_FEATS;
    float* Wc    = sm + OFF_WC;
    float* score = sm + OFF_SCORE;
    float* tvec  = sm + OFF_TVEC;
    int*   slist = (int*)(sm + OFF_SLIST);
    int*   scnt  = (int*)(sm + OFF_SCNT);
    float* rdout = sm + OFF_RD;
    float* t1    = sm + OFF_T1;
    float* t2    = sm + OFF_T2;
    float* was   = sm + OFF_WAS;

    const int g    = blockIdx.x;
    const int tid  = threadIdx.x;
    const int w    = tid >> 5;
    const int lane = tid & 31;
    const int wr   = w & 3, wc = w >> 2;
    const int lr   = lane & 3, lc = lane >> 2;
    const int base = g * NPG;
    const int row8 = tid >> 3;  // 0..63 (8 threads/row helpers)
    const int l8   = tid & 7;

    // ---- build binary adjacency (symmetrized), padded stride SA ----
    for (int i = tid; i < NPG * SA; i += NT) A[i] = 0.f;
    if (tid == 0) *scnt = 0;
    __syncthreads();
    {
        const int* es = ei + g * EPG;
        const int* ed = ei + ETOT + g * EPG;
        for (int e = tid; e < EPG; e += NT) {
            int s = es[e] - base;
            int d = ed[e] - base;
            A[s * SA + d] = 1.f;
            A[d * SA + s] = 1.f;
        }
    }
    __syncthreads();
    if (tid < 64) A[tid * SA + tid] += 1.f;  // A += I (diag may reach 2)
    __syncthreads();
    {   // rowsum -> dinv
        float s = 0.f;
#pragma unroll
        for (int k = l8; k < 64; k += 8) s += A[row8 * SA + k];
        s += __shfl_xor_sync(0xFFFFFFFFu, s, 1);
        s += __shfl_xor_sync(0xFFFFFFFFu, s, 2);
        s += __shfl_xor_sync(0xFFFFFFFFu, s, 4);
        if (l8 == 0) tvec[row8] = rsqrtf(s);
    }
    __syncthreads();
    for (int i = tid; i < NPG * NPG; i += NT) {
        int r = i >> 6, c = i & 63;
        A[r * SA + c] *= tvec[r] * tvec[c];
    }
    // x tile into padded xs (ordered before use by gemm's internal syncs)
    for (int i = tid; i < NPG * HD; i += NT)
        xs[(i >> 7) * SX + (i & 127)] = x[base * HD + i];
    if (tid < FD) was[tid] = Wa[tid];

    // ---- 3 GCN layers ----
    gemm_xw(xs, SX, W1, Wc, tmpI, tid, wr, wc, lr, lc);
    amult_relu(A, tmpI, b1, feats + 0, wr, wc, lr, lc);
    gemm_xw(feats + 0, SF, W2, Wc, tmpI, tid, wr, wc, lr, lc);
    amult_relu(A, tmpI, b2, feats + 128, wr, wc, lr, lc);
    gemm_xw(feats + 128, SF, W3, Wc, tmpI, tid, wr, wc, lr, lc);
    amult_relu(A, tmpI, b3, feats + 256, wr, wc, lr, lc);

    // ---- attention: score = tanh(A @ (feats @ Wa) + ba) ----
    {
        float p = 0.f;
#pragma unroll
        for (int c = l8; c < FD; c += 8) p = fmaf(feats[row8 * SF + c], was[c], p);
        p += __shfl_xor_sync(0xFFFFFFFFu, p, 1);
        p += __shfl_xor_sync(0xFFFFFFFFu, p, 2);
        p += __shfl_xor_sync(0xFFFFFFFFu, p, 4);
        if (l8 == 0) tvec[row8] = p;
    }
    __syncthreads();
    {
        float s = 0.f;
#pragma unroll
        for (int k = l8; k < 64; k += 8) s = fmaf(A[row8 * SA + k], tvec[k], s);
        s += __shfl_xor_sync(0xFFFFFFFFu, s, 1);
        s += __shfl_xor_sync(0xFFFFFFFFu, s, 2);
        s += __shfl_xor_sync(0xFFFFFFFFu, s, 4);
        if (l8 == 0) score[row8] = tanhf(s + ba[0]);
    }
    __syncthreads();
    // ---- top-K (jax tie-break: smaller index wins among equals) ----
    if (tid < 64) {
        float si = score[tid];
        int rank = 0;
#pragma unroll
        for (int j = 0; j < 64; ++j) {
            float sj = score[j];
            rank += (sj > si) || (sj == si && j < tid);
        }
        if (rank < KSEL) {
            int p = atomicAdd(scnt, 1);
            slist[p] = tid;  // unordered OK: mean & max order-invariant
        }
    }
    __syncthreads();
    // ---- readout: mean || max of feats*score over selected ----
    if (tid < FD) {
        float ssum = 0.f, mx = -FLT_MAX;
#pragma unroll
        for (int j = 0; j < KSEL; ++j) {
            int i = slist[j];
            float v = feats[i * SF + tid] * score[i];
            ssum += v;
            mx = fmaxf(mx, v);
        }
        rdout[tid]      = ssum * (1.f / (float)KSEL);
        rdout[FD + tid] = mx;
    }
    __syncthreads();
    // ---- MLP layer 1: [768] -> [128] ----
    {
        float* psum = Wc;
        int j = tid & 127, q = tid >> 7;
        float a = 0.f;
        for (int c = q * 192; c < q * 192 + 192; ++c)
            a = fmaf(rdout[c], M1[c * HD + j], a);
        psum[tid] = a;
        __syncthreads();
        if (tid < 128)
            t1[tid] = fmaxf(psum[tid] + psum[tid + 128] + psum[tid + 256] + psum[tid + 384] + c1[tid], 0.f);
    }
    __syncthreads();
    // ---- MLP layer 2: [128] -> [64] ----
    {
        float* psum = Wc;
        int j = tid & 63, q = tid >> 6;
        float a = 0.f;
#pragma unroll
        for (int c = q * 16; c < q * 16 + 16; ++c)
            a = fmaf(t1[c], M2[c * 64 + j], a);
        psum[tid] = a;
        __syncthreads();
        if (tid < 64) {
            float s = c2[tid];
#pragma unroll
            for (int q2 = 0; q2 < 8; ++q2) s += psum[tid + q2 * 64];
            t2[tid] = fmaxf(s, 0.f);
        }
    }
    __syncthreads();
    // ---- MLP layer 3: [64] -> [10] ----
    if (tid < DOUT) {
        float a = c3[tid];
#pragma unroll
        for (int c = 0; c < 64; ++c) a = fmaf(t2[c], M3[c * DOUT + tid], a);
        out[g * DOUT + tid] = a;
    }
}

extern "C" void kernel_launch(void* const* d_in, const int* in_sizes, int n_in,
                              void* d_out, int out_size)
{
    const float* x  = (const float*)d_in[0];
    const int*   ei = (const int*)d_in[1];
    // d_in[2] = batch (unused: graphs are contiguous 64-node blocks)
    const float* W1 = (const float*)d_in[3];
    const float* b1 = (const float*)d_in[4];
    const float* W2 = (const float*)d_in[5];
    const float* b2 = (const float*)d_in[6];
    const float* W3 = (const float*)d_in[7];
    const float* b3 = (const float*)d_in[8];
    const float* Wa = (const float*)d_in[9];
    const float* ba = (const float*)d_in[10];
    const float* M1 = (const float*)d_in[11];
    const float* c1 = (const float*)d_in[12];
    const float* M2 = (const float*)d_in[13];
    const float* c2 = (const float*)d_in[14];
    const float* M3 = (const float*)d_in[15];
    const float* c3 = (const float*)d_in[16];
    float* out = (float*)d_out;

    const int smem_bytes = SMEM_FLOATS * (int)sizeof(float);
    cudaFuncSetAttribute(sagpool_kernel,
                         cudaFuncAttributeMaxDynamicSharedMemorySize, smem_bytes);
    sagpool_kernel<<<NG, NT, smem_bytes>>>(x, ei, W1, b1, W2, b2, W3, b3,
                                           Wa, ba, M1, c1, M2, c2, M3, c3, out);
}

// round 8
// speedup vs baseline: 1.0329x; 1.0329x over previous
#include <cuda_runtime.h>
#include <float.h>

// Problem constants (fixed shapes)
#define NG    128
#define NPG   64
#define EPG   1024
#define ETOT  131072
#define HD    128
#define FD    384      // 3*H
#define KSEL  32
#define DOUT  10
#define NT    512      // 16 warps

// padded row strides (floats) — all ≡ 4 (mod 32) banks: 4 consecutive rows hit distinct banks
#define SA    68       // adjacency
#define SX    132      // x tile
#define ST    132      // tmp (A@ operand)
#define SF    388      // feats

// Shared memory layout (float indices)
#define OFF_A     0                       // 64*68  = 4352
#define OFF_XS    4352                    // 64*132 = 8448
#define OFF_TMP   12800                   // 64*132 = 8448
#define OFF_FEATS 21248                   // 64*388 = 24832
#define OFF_WC    46080                   // 64*128 = 8192 W stage (reused as psum[512])
#define OFF_SCORE 54272                   // 64
#define OFF_TVEC  54336                   // 64
#define OFF_SLIST 54400                   // 32 (int)
#define OFF_SCNT  54432                   // 4
#define OFF_RD    54436                   // 768
#define OFF_T1    55204                   // 128
#define OFF_T2    55332                   // 64
#define OFF_WAS   55396                   // 384
#define SMEM_FLOATS 55780                 // 223120 bytes

__device__ __forceinline__ void fma4(float4& acc, float s, const float4& v)
{
    acc.x = fmaf(s, v.x, acc.x);
    acc.y = fmaf(s, v.y, acc.y);
    acc.z = fmaf(s, v.z, acc.z);
    acc.w = fmaf(s, v.w, acc.w);
}

// ---------------------------------------------------------------------------
// tmp[64][ST] = In[64][128](smem, row stride inStride) @ Wg[128][128](global, staged)
// warp tile 16 rows (wr) x 32 cols (wc); thread tile 4x4 (lr, lc)
// ---------------------------------------------------------------------------
__device__ __forceinline__ void gemm_xw(const float* __restrict__ In, int inStride,
                                        const float* __restrict__ Wg,
                                        float* __restrict__ Wc, float* __restrict__ tmp,
                                        int tid, int wr, int wc, int lr, int lc)
{
    float4 acc[4];
#pragma unroll
    for (int r = 0; r < 4; ++r) acc[r] = make_float4(0.f, 0.f, 0.f, 0.f);

    const int colBase = wc * 32 + lc * 4;
    const int row0    = wr * 16 + lr;          // rows row0, row0+4, row0+8, row0+12
    const float4* Wc4 = (const float4*)Wc;

    for (int kc = 0; kc < 128; kc += 64) {
        __syncthreads();  // protect Wc reuse; orders feats/tmp writes before reads
        {   // stage 64x128 chunk of W (plain row-major)
            const float4* src = (const float4*)(Wg + kc * HD);
            float4* dst = (float4*)Wc;
#pragma unroll
            for (int i = 0; i < 4; ++i) dst[tid + i * NT] = src[tid + i * NT];
        }
        __syncthreads();
#pragma unroll 4
        for (int k = 0; k < 64; k += 4) {
            // A operand: float4 along k; 4 distinct rows per warp (4-bank spread), 8-way bcast
            float4 a0 = *(const float4*)(In + (row0 + 0) * inStride + kc + k);
            float4 a1 = *(const float4*)(In + (row0 + 4) * inStride + kc + k);
            float4 a2 = *(const float4*)(In + (row0 + 8) * inStride + kc + k);
            float4 a3 = *(const float4*)(In + (row0 + 12) * inStride + kc + k);
            // W operand: 32 cols per warp -> 128B unique per load (4-way lr bcast)
            float4 w0 = Wc4[((k + 0) * HD + colBase) >> 2];
            float4 w1 = Wc4[((k + 1) * HD + colBase) >> 2];
            float4 w2 = Wc4[((k + 2) * HD + colBase) >> 2];
            float4 w3 = Wc4[((k + 3) * HD + colBase) >> 2];
            fma4(acc[0], a0.x, w0); fma4(acc[0], a0.y, w1); fma4(acc[0], a0.z, w2); fma4(acc[0], a0.w, w3);
            fma4(acc[1], a1.x, w0); fma4(acc[1], a1.y, w1); fma4(acc[1], a1.z, w2); fma4(acc[1], a1.w, w3);
            fma4(acc[2], a2.x, w0); fma4(acc[2], a2.y, w1); fma4(acc[2], a2.z, w2); fma4(acc[2], a2.w, w3);
            fma4(acc[3], a3.x, w0); fma4(acc[3], a3.y, w1); fma4(acc[3], a3.z, w2); fma4(acc[3], a3.w, w3);
        }
    }
    __syncthreads();
#pragma unroll
    for (int r = 0; r < 4; ++r)
        *(float4*)(tmp + (row0 + 4 * r) * ST + colBase) = acc[r];
}

// ---------------------------------------------------------------------------
// featsDst[64][SF] = relu(A[64][64](stride SA) @ tmp[64][ST] + b)
// ---------------------------------------------------------------------------
__device__ __forceinline__ void amult_relu(const float* __restrict__ A,
                                           const float* __restrict__ tmp,
                                           const float* __restrict__ bvec,
                                           float* __restrict__ featsDst,
                                           int wr, int wc, int lr, int lc)
{
    float4 acc[4];
#pragma unroll
    for (int r = 0; r < 4; ++r) acc[r] = make_float4(0.f, 0.f, 0.f, 0.f);

    const int colBase = wc * 32 + lc * 4;
    const int row0    = wr * 16 + lr;
    __syncthreads();  // tmp ready
#pragma unroll 4
    for (int k = 0; k < 64; k += 4) {
        float4 a0 = *(const float4*)(A + (row0 + 0) * SA + k);
        float4 a1 = *(const float4*)(A + (row0 + 4) * SA + k);
        float4 a2 = *(const float4*)(A + (row0 + 8) * SA + k);
        float4 a3 = *(const float4*)(A + (row0 + 12) * SA + k);
        float4 t0 = *(const float4*)(tmp + (k + 0) * ST + colBase);
        float4 t1 = *(const float4*)(tmp + (k + 1) * ST + colBase);
        float4 t2 = *(const float4*)(tmp + (k + 2) * ST + colBase);
        float4 t3 = *(const float4*)(tmp + (k + 3) * ST + colBase);
        fma4(acc[0], a0.x, t0); fma4(acc[0], a0.y, t1); fma4(acc[0], a0.z, t2); fma4(acc[0], a0.w, t3);
        fma4(acc[1], a1.x, t0); fma4(acc[1], a1.y, t1); fma4(acc[1], a1.z, t2); fma4(acc[1], a1.w, t3);
        fma4(acc[2], a2.x, t0); fma4(acc[2], a2.y, t1); fma4(acc[2], a2.z, t2); fma4(acc[2], a2.w, t3);
        fma4(acc[3], a3.x, t0); fma4(acc[3], a3.y, t1); fma4(acc[3], a3.z, t2); fma4(acc[3], a3.w, t3);
    }
    float4 bb = *(const float4*)(bvec + colBase);
#pragma unroll
    for (int r = 0; r < 4; ++r) {
        float4 v;
        v.x = fmaxf(acc[r].x + bb.x, 0.f);
        v.y = fmaxf(acc[r].y + bb.y, 0.f);
        v.z = fmaxf(acc[r].z + bb.z, 0.f);
        v.w = fmaxf(acc[r].w + bb.w, 0.f);
        *(float4*)(featsDst + (row0 + 4 * r) * SF + colBase) = v;
    }
    __syncthreads();
}

__global__ void __launch_bounds__(NT, 1)
sagpool_kernel(const float* __restrict__ x, const int* __restrict__ ei,
               const float* __restrict__ W1, const float* __restrict__ b1,
               const float* __restrict__ W2, const float* __restrict__ b2,
               const float* __restrict__ W3, const float* __restrict__ b3,
               const float* __restrict__ Wa, const float* __restrict__ ba,
               const float* __restrict__ M1, const float* __restrict__ c1,
               const float* __restrict__ M2, const float* __restrict__ c2,
               const float* __restrict__ M3, const float* __restrict__ c3,
               float* __restrict__ out)
{
    extern __shared__ float sm[];
    float* A     = sm + OFF_A;
    float* xs    = sm + OFF_XS;
    float* tmp   = sm + OFF_TMP;
    float* feats = sm + OFF_FEATS;
    float* Wc    = sm + OFF_WC;
    float* score = sm + OFF_SCORE;
    float* tvec  = sm + OFF_TVEC;
    int*   slist = (int*)(sm + OFF_SLIST);
    int*   scnt  = (int*)(sm + OFF_SCNT);
    float* rdout = sm + OFF_RD;
    float* t1    = sm + OFF_T1;
    float* t2    = sm + OFF_T2;
    float* was   = sm + OFF_WAS;

    const int g    = blockIdx.x;
    const int tid  = threadIdx.x;
    const int w    = tid >> 5;
    const int lane = tid & 31;
    const int wr   = w & 3, wc = w >> 2;
    const int lr   = lane & 3, lc = lane >> 2;
    const int base = g * NPG;
    const int row8 = tid >> 3;  // 0..63 (8 threads/row helpers)
    const int l8   = tid & 7;

    // ---- build binary adjacency (symmetrized), padded stride SA ----
    for (int i = tid; i < NPG * SA; i += NT) A[i] = 0.f;
    if (tid == 0) *scnt = 0;
    __syncthreads();
    {
        const int* es = ei + g * EPG;
        const int* ed = ei + ETOT + g * EPG;
        for (int e = tid; e < EPG; e += NT) {
            int s = es[e] - base;
            int d = ed[e] - base;
            A[s * SA + d] = 1.f;
            A[d * SA + s] = 1.f;
        }
    }
    __syncthreads();
    if (tid < 64) A[tid * SA + tid] += 1.f;  // A += I (diag may reach 2)
    __syncthreads();
    {   // rowsum -> dinv
        float s = 0.f;
#pragma unroll
        for (int k = l8; k < 64; k += 8) s += A[row8 * SA + k];
        s += __shfl_xor_sync(0xFFFFFFFFu, s, 1);
        s += __shfl_xor_sync(0xFFFFFFFFu, s, 2);
        s += __shfl_xor_sync(0xFFFFFFFFu, s, 4);
        if (l8 == 0) tvec[row8] = rsqrtf(s);
    }
    __syncthreads();
    for (int i = tid; i < NPG * NPG; i += NT) {
        int r = i >> 6, c = i & 63;
        A[r * SA + c] *= tvec[r] * tvec[c];
    }
    // x tile into padded xs (ordered before use by gemm's internal syncs)
    for (int i = tid; i < NPG * HD; i += NT)
        xs[(i >> 7) * SX + (i & 127)] = x[base * HD + i];
    if (tid < FD) was[tid] = Wa[tid];

    // ---- 3 GCN layers: h = relu(A @ (In @ W) + b) ----
    gemm_xw(xs, SX, W1, Wc, tmp, tid, wr, wc, lr, lc);
    amult_relu(A, tmp, b1, feats + 0, wr, wc, lr, lc);
    gemm_xw(feats + 0, SF, W2, Wc, tmp, tid, wr, wc, lr, lc);
    amult_relu(A, tmp, b2, feats + 128, wr, wc, lr, lc);
    gemm_xw(feats + 128, SF, W3, Wc, tmp, tid, wr, wc, lr, lc);
    amult_relu(A, tmp, b3, feats + 256, wr, wc, lr, lc);

    // ---- attention: score = tanh(A @ (feats @ Wa) + ba) ----
    {
        float p = 0.f;
#pragma unroll
        for (int c = l8; c < FD; c += 8) p = fmaf(feats[row8 * SF + c], was[c], p);
        p += __shfl_xor_sync(0xFFFFFFFFu, p, 1);
        p += __shfl_xor_sync(0xFFFFFFFFu, p, 2);
        p += __shfl_xor_sync(0xFFFFFFFFu, p, 4);
        if (l8 == 0) tvec[row8] = p;
    }
    __syncthreads();
    {
        float s = 0.f;
#pragma unroll
        for (int k = l8; k < 64; k += 8) s = fmaf(A[row8 * SA + k], tvec[k], s);
        s += __shfl_xor_sync(0xFFFFFFFFu, s, 1);
        s += __shfl_xor_sync(0xFFFFFFFFu, s, 2);
        s += __shfl_xor_sync(0xFFFFFFFFu, s, 4);
        if (l8 == 0) score[row8] = tanhf(s + ba[0]);
    }
    __syncthreads();
    // ---- top-K (jax tie-break: smaller index wins among equals) ----
    if (tid < 64) {
        float si = score[tid];
        int rank = 0;
#pragma unroll
        for (int j = 0; j < 64; ++j) {
            float sj = score[j];
            rank += (sj > si) || (sj == si && j < tid);
        }
        if (rank < KSEL) {
            int p = atomicAdd(scnt, 1);
            slist[p] = tid;  // unordered OK: mean & max order-invariant
        }
    }
    __syncthreads();
    // ---- readout: mean || max of feats*score over selected ----
    if (tid < FD) {
        float ssum = 0.f, mx = -FLT_MAX;
#pragma unroll
        for (int j = 0; j < KSEL; ++j) {
            int i = slist[j];
            float v = feats[i * SF + tid] * score[i];
            ssum += v;
            mx = fmaxf(mx, v);
        }
        rdout[tid]      = ssum * (1.f / (float)KSEL);
        rdout[FD + tid] = mx;
    }
    __syncthreads();
    // ---- MLP layer 1: [768] -> [128] ----
    {
        float* psum = Wc;
        int j = tid & 127, q = tid >> 7;
        float a = 0.f;
        for (int c = q * 192; c < q * 192 + 192; ++c)
            a = fmaf(rdout[c], M1[c * HD + j], a);
        psum[tid] = a;
        __syncthreads();
        if (tid < 128)
            t1[tid] = fmaxf(psum[tid] + psum[tid + 128] + psum[tid + 256] + psum[tid + 384] + c1[tid], 0.f);
    }
    __syncthreads();
    // ---- MLP layer 2: [128] -> [64] ----
    {
        float* psum = Wc;
        int j = tid & 63, q = tid >> 6;
        float a = 0.f;
#pragma unroll
        for (int c = q * 16; c < q * 16 + 16; ++c)
            a = fmaf(t1[c], M2[c * 64 + j], a);
        psum[tid] = a;
        __syncthreads();
        if (tid < 64) {
            float s = c2[tid];
#pragma unroll
            for (int q2 = 0; q2 < 8; ++q2) s += psum[tid + q2 * 64];
            t2[tid] = fmaxf(s, 0.f);
        }
    }
    __syncthreads();
    // ---- MLP layer 3: [64] -> [10] ----
    if (tid < DOUT) {
        float a = c3[tid];
#pragma unroll
        for (int c = 0; c < 64; ++c) a = fmaf(t2[c], M3[c * DOUT + tid], a);
        out[g * DOUT + tid] = a;
    }
}

extern "C" void kernel_launch(void* const* d_in, const int* in_sizes, int n_in,
                              void* d_out, int out_size)
{
    const float* x  = (const float*)d_in[0];
    const int*   ei = (const int*)d_in[1];
    // d_in[2] = batch (unused: graphs are contiguous 64-node blocks)
    const float* W1 = (const float*)d_in[3];
    const float* b1 = (const float*)d_in[4];
    const float* W2 = (const float*)d_in[5];
    const float* b2 = (const float*)d_in[6];
    const float* W3 = (const float*)d_in[7];
    const float* b3 = (const float*)d_in[8];
    const float* Wa = (const float*)d_in[9];
    const float* ba = (const float*)d_in[10];
    const float* M1 = (const float*)d_in[11];
    const float* c1 = (const float*)d_in[12];
    const float* M2 = (const float*)d_in[13];
    const float* c2 = (const float*)d_in[14];
    const float* M3 = (const float*)d_in[15];
    const float* c3 = (const float*)d_in[16];
    float* out = (float*)d_out;

    const int smem_bytes = SMEM_FLOATS * (int)sizeof(float);
    cudaFuncSetAttribute(sagpool_kernel,
                         cudaFuncAttributeMaxDynamicSharedMemorySize, smem_bytes);
    sagpool_kernel<<<NG, NT, smem_bytes>>>(x, ei, W1, b1, W2, b2, W3, b3,
                                           Wa, ba, M1, c1, M2, c2, M3, c3, out);
}